// round 3
// baseline (speedup 1.0000x reference)
#include <cuda_runtime.h>
#include <math.h>

// Problem constants (fixed by dataset)
#define NN 50000      // nodes
#define NE 800000     // edges (before self loops)
#define DIM 128
#define HEADS 4
#define HD 32
#define NEG 0.2f
#define LNEPS 1e-5f

// ---------------- scratch (device globals; no allocation allowed) -----------
__device__ float g_xl[NN * DIM];
__device__ float g_xr[NN * DIM];
__device__ int   g_cnt[NN];
__device__ int   g_row[NN];
__device__ int   g_cur[NN];
__device__ int   g_csr[NE];

// ---------------- packed fp32x2 FMA (2x fp32 rate on sm_103a) ---------------
__device__ __forceinline__ void ffma2(float2& d, const float2 a, const float2 b) {
    unsigned long long& dd = reinterpret_cast<unsigned long long&>(d);
    unsigned long long aa = reinterpret_cast<const unsigned long long&>(a);
    unsigned long long bb = reinterpret_cast<const unsigned long long&>(b);
    asm("fma.rn.f32x2 %0, %1, %2, %0;" : "+l"(dd) : "l"(aa), "l"(bb));
}

// ---------------- GEMM: xl = x @ W_l, xr = x @ W_r  -------------------------
// Block: 256 threads, 64 rows. smem: W combined [128][256] + x^T [128][68].
#define GR 64
#define XS 68
#define GEMM_SMEM ((128 * 256 + 128 * XS) * 4)

__global__ void __launch_bounds__(256) gemm_kernel(const float* __restrict__ x,
                                                   const float* __restrict__ Wl,
                                                   const float* __restrict__ Wr) {
    extern __shared__ float sm[];
    float* sW = sm;                 // [k][cc], cc<128 -> Wl col, else Wr col
    float* sX = sm + 128 * 256;     // transposed: [k][r] with row stride XS

    const int tid = threadIdx.x;
    const int r0 = blockIdx.x * GR;

    for (int i = tid; i < 128 * 256; i += 256) {
        int k = i >> 8, cc = i & 255;
        sW[i] = (cc < 128) ? Wl[k * 128 + cc] : Wr[k * 128 + (cc - 128)];
    }
    for (int i = tid; i < GR * 128; i += 256) {
        int r = i >> 7, k = i & 127;
        int row = r0 + r;
        sX[k * XS + r] = (row < NN) ? x[row * 128 + k] : 0.f;
    }
    __syncthreads();

    const int lane = tid & 31;
    const int w = tid >> 5;

    float2 accA[8][2], accB[8][2];
#pragma unroll
    for (int r = 0; r < 8; r++) {
        accA[r][0] = make_float2(0.f, 0.f); accA[r][1] = make_float2(0.f, 0.f);
        accB[r][0] = make_float2(0.f, 0.f); accB[r][1] = make_float2(0.f, 0.f);
    }

#pragma unroll 4
    for (int k = 0; k < 128; k++) {
        const float4 wa = *(const float4*)&sW[k * 256 + lane * 4];
        const float4 wb = *(const float4*)&sW[k * 256 + 128 + lane * 4];
        const float4 x0 = *(const float4*)&sX[k * XS + w * 8];
        const float4 x1 = *(const float4*)&sX[k * XS + w * 8 + 4];
        float xs[8] = {x0.x, x0.y, x0.z, x0.w, x1.x, x1.y, x1.z, x1.w};
        const float2 wa0 = make_float2(wa.x, wa.y), wa1 = make_float2(wa.z, wa.w);
        const float2 wb0 = make_float2(wb.x, wb.y), wb1 = make_float2(wb.z, wb.w);
#pragma unroll
        for (int r = 0; r < 8; r++) {
            const float2 xx = make_float2(xs[r], xs[r]);
            ffma2(accA[r][0], xx, wa0);
            ffma2(accA[r][1], xx, wa1);
            ffma2(accB[r][0], xx, wb0);
            ffma2(accB[r][1], xx, wb1);
        }
    }

#pragma unroll
    for (int r = 0; r < 8; r++) {
        int row = r0 + w * 8 + r;
        if (row < NN) {
            *(float4*)&g_xl[row * 128 + lane * 4] =
                make_float4(accA[r][0].x, accA[r][0].y, accA[r][1].x, accA[r][1].y);
            *(float4*)&g_xr[row * 128 + lane * 4] =
                make_float4(accB[r][0].x, accB[r][0].y, accB[r][1].x, accB[r][1].y);
        }
    }
}

// ---------------- CSR build --------------------------------------------------
__global__ void zero_cnt_kernel() {
    int i = blockIdx.x * blockDim.x + threadIdx.x;
    if (i < NN) g_cnt[i] = 0;
}

__global__ void hist_kernel(const int* __restrict__ dst) {
    int e = blockIdx.x * blockDim.x + threadIdx.x;
    if (e < NE) atomicAdd(&g_cnt[dst[e]], 1);
}

__global__ void __launch_bounds__(1024) scan_kernel() {
    __shared__ int sp[1024];
    const int tid = threadIdx.x;
    const int CH = (NN + 1023) / 1024;  // 49
    const int base = tid * CH;
    int s = 0;
    for (int i = 0; i < CH; i++) {
        int n = base + i;
        if (n < NN) s += g_cnt[n];
    }
    sp[tid] = s;
    __syncthreads();
    for (int off = 1; off < 1024; off <<= 1) {
        int v = (tid >= off) ? sp[tid - off] : 0;
        __syncthreads();
        sp[tid] += v;
        __syncthreads();
    }
    int run = (tid > 0) ? sp[tid - 1] : 0;
    for (int i = 0; i < CH; i++) {
        int n = base + i;
        if (n < NN) {
            g_row[n] = run;
            g_cur[n] = run;
            run += g_cnt[n];
        }
    }
}

__global__ void scatter_kernel(const int* __restrict__ src, const int* __restrict__ dst) {
    int e = blockIdx.x * blockDim.x + threadIdx.x;
    if (e < NE) {
        int d = dst[e];
        int pos = atomicAdd(&g_cur[d], 1);
        g_csr[pos] = src[e];
    }
}

// ---------------- fused aggregation: online segment-softmax + ELU + LN ------
// One warp per node. lane layout: head = lane>>3, dims = (lane&7)*4 .. +3
// so the per-lane float4 at node*128 + lane*4 covers exactly those dims.
__device__ __forceinline__ float lrelu(float v) { return v > 0.f ? v : NEG * v; }

__global__ void __launch_bounds__(256) agg_kernel(const float* __restrict__ att,
                                                  const float* __restrict__ bias,
                                                  const float* __restrict__ gamma,
                                                  const float* __restrict__ beta,
                                                  float* __restrict__ out) {
    const int node = blockIdx.x * 8 + (threadIdx.x >> 5);
    if (node >= NN) return;
    const int lane = threadIdx.x & 31;
    const unsigned FULL = 0xffffffffu;

    const float4 a4 = *(const float4*)&att[lane * 4];
    const float4 xr4 = *(const float4*)&g_xr[node * 128 + lane * 4];

    float m = -INFINITY, s = 0.f;
    float4 acc = make_float4(0.f, 0.f, 0.f, 0.f);

    const int start = g_row[node];
    const int deg = g_cnt[node];

    // ---- self-loop (src = node), processed in straight-line code ----
    {
        const float4 xl4 = *(const float4*)&g_xl[node * 128 + lane * 4];
        float hx = lrelu(xl4.x + xr4.x);
        float hy = lrelu(xl4.y + xr4.y);
        float hz = lrelu(xl4.z + xr4.z);
        float hw = lrelu(xl4.w + xr4.w);
        float p = hx * a4.x + hy * a4.y + hz * a4.z + hw * a4.w;
        p += __shfl_xor_sync(FULL, p, 1);
        p += __shfl_xor_sync(FULL, p, 2);
        p += __shfl_xor_sync(FULL, p, 4);
        m = p;
        s = 1.f;                      // wgt = exp(p - m) = 1
        acc.x = xl4.x; acc.y = xl4.y; acc.z = xl4.z; acc.w = xl4.w;
    }

    // ---- CSR edges in chunks of 32 ----
    for (int ebase = 0; ebase < deg; ebase += 32) {
        const int idx = ebase + lane;
        const int my_src = (idx < deg) ? g_csr[start + idx] : 0;
        const int cnt = min(32, deg - ebase);
#pragma unroll 1
        for (int i = 0; i < cnt; i++) {
            const int src = __shfl_sync(FULL, my_src, i);
            const float4 xl4 = *(const float4*)&g_xl[src * 128 + lane * 4];
            float hx = lrelu(xl4.x + xr4.x);
            float hy = lrelu(xl4.y + xr4.y);
            float hz = lrelu(xl4.z + xr4.z);
            float hw = lrelu(xl4.w + xr4.w);
            float p = hx * a4.x + hy * a4.y + hz * a4.z + hw * a4.w;
            p += __shfl_xor_sync(FULL, p, 1);
            p += __shfl_xor_sync(FULL, p, 2);
            p += __shfl_xor_sync(FULL, p, 4);  // logit, replicated in 8-lane head group
            if (p > m) {
                float sc = __expf(m - p);
                s *= sc;
                acc.x *= sc; acc.y *= sc; acc.z *= sc; acc.w *= sc;
                m = p;
            }
            float wgt = __expf(p - m);
            s += wgt;
            acc.x = fmaf(wgt, xl4.x, acc.x);
            acc.y = fmaf(wgt, xl4.y, acc.y);
            acc.z = fmaf(wgt, xl4.z, acc.z);
            acc.w = fmaf(wgt, xl4.w, acc.w);
        }
    }

    // epilogue: normalize, bias, ELU, LayerNorm — all inside this warp
    const float inv = 1.f / s;
    const float4 b4 = *(const float4*)&bias[lane * 4];
    float4 o;
    o.x = acc.x * inv + b4.x;
    o.y = acc.y * inv + b4.y;
    o.z = acc.z * inv + b4.z;
    o.w = acc.w * inv + b4.w;
    o.x = o.x > 0.f ? o.x : (__expf(o.x) - 1.f);
    o.y = o.y > 0.f ? o.y : (__expf(o.y) - 1.f);
    o.z = o.z > 0.f ? o.z : (__expf(o.z) - 1.f);
    o.w = o.w > 0.f ? o.w : (__expf(o.w) - 1.f);

    float t = o.x + o.y + o.z + o.w;
#pragma unroll
    for (int off = 1; off < 32; off <<= 1) t += __shfl_xor_sync(FULL, t, off);
    const float mu = t * (1.f / 128.f);

    float dx = o.x - mu, dy = o.y - mu, dz = o.z - mu, dw = o.w - mu;
    float v = dx * dx + dy * dy + dz * dz + dw * dw;
#pragma unroll
    for (int off = 1; off < 32; off <<= 1) v += __shfl_xor_sync(FULL, v, off);
    const float rstd = rsqrtf(v * (1.f / 128.f) + LNEPS);

    const float4 g4 = *(const float4*)&gamma[lane * 4];
    const float4 be4 = *(const float4*)&beta[lane * 4];
    o.x = dx * rstd * g4.x + be4.x;
    o.y = dy * rstd * g4.y + be4.y;
    o.z = dz * rstd * g4.z + be4.z;
    o.w = dw * rstd * g4.w + be4.w;
    *(float4*)&out[node * 128 + lane * 4] = o;
}

// ---------------- launch -----------------------------------------------------
extern "C" void kernel_launch(void* const* d_in, const int* in_sizes, int n_in,
                              void* d_out, int out_size) {
    const float* x     = (const float*)d_in[0];
    const int*   ei    = (const int*)d_in[1];   // [2, NE]: src row then dst row
    const float* Wl    = (const float*)d_in[2];
    const float* Wr    = (const float*)d_in[3];
    const float* att   = (const float*)d_in[4];
    const float* bias  = (const float*)d_in[5];
    const float* gamma = (const float*)d_in[6];
    const float* beta  = (const float*)d_in[7];
    float* out = (float*)d_out;

    const int* src = ei;
    const int* dst = ei + NE;

    cudaFuncSetAttribute(gemm_kernel, cudaFuncAttributeMaxDynamicSharedMemorySize, GEMM_SMEM);

    zero_cnt_kernel<<<(NN + 255) / 256, 256>>>();
    hist_kernel<<<(NE + 255) / 256, 256>>>(dst);
    scan_kernel<<<1, 1024>>>();
    scatter_kernel<<<(NE + 255) / 256, 256>>>(src, dst);
    gemm_kernel<<<(NN + GR - 1) / GR, 256, GEMM_SMEM>>>(x, Wl, Wr);
    agg_kernel<<<(NN + 7) / 8, 256>>>(att, bias, gamma, beta, out);
}

// round 4
// speedup vs baseline: 1.0342x; 1.0342x over previous
#include <cuda_runtime.h>
#include <math.h>

// Problem constants (fixed by dataset)
#define NN 50000      // nodes
#define NE 800000     // edges (before self loops)
#define DIM 128
#define HEADS 4
#define HD 32
#define NEG 0.2f
#define LNEPS 1e-5f

// ---------------- scratch (device globals; no allocation allowed) -----------
__device__ float g_xl[NN * DIM];
__device__ float g_xr[NN * DIM];
__device__ int   g_cnt[NN];
__device__ int   g_row[NN];
__device__ int   g_cur[NN];
__device__ int   g_csr[NE];

// ---------------- packed fp32x2 FMA (2x fp32 rate on sm_103a) ---------------
__device__ __forceinline__ void ffma2(float2& d, const float2 a, const float2 b) {
    unsigned long long& dd = reinterpret_cast<unsigned long long&>(d);
    unsigned long long aa = reinterpret_cast<const unsigned long long&>(a);
    unsigned long long bb = reinterpret_cast<const unsigned long long&>(b);
    asm("fma.rn.f32x2 %0, %1, %2, %0;" : "+l"(dd) : "l"(aa), "l"(bb));
}

// ---------------- GEMM: xl = x @ W_l, xr = x @ W_r  -------------------------
// Block: 256 threads, 64 rows. smem: W combined [128][256] + x^T [128][68].
#define GR 64
#define XS 68
#define GEMM_SMEM ((128 * 256 + 128 * XS) * 4)

__global__ void __launch_bounds__(256) gemm_kernel(const float* __restrict__ x,
                                                   const float* __restrict__ Wl,
                                                   const float* __restrict__ Wr) {
    extern __shared__ float sm[];
    float* sW = sm;                 // [k][cc], cc<128 -> Wl col, else Wr col
    float* sX = sm + 128 * 256;     // transposed: [k][r] with row stride XS

    const int tid = threadIdx.x;
    const int r0 = blockIdx.x * GR;

    for (int i = tid; i < 128 * 256; i += 256) {
        int k = i >> 8, cc = i & 255;
        sW[i] = (cc < 128) ? Wl[k * 128 + cc] : Wr[k * 128 + (cc - 128)];
    }
    for (int i = tid; i < GR * 128; i += 256) {
        int r = i >> 7, k = i & 127;
        int row = r0 + r;
        sX[k * XS + r] = (row < NN) ? x[row * 128 + k] : 0.f;
    }
    __syncthreads();

    const int lane = tid & 31;
    const int w = tid >> 5;

    float2 accA[8][2], accB[8][2];
#pragma unroll
    for (int r = 0; r < 8; r++) {
        accA[r][0] = make_float2(0.f, 0.f); accA[r][1] = make_float2(0.f, 0.f);
        accB[r][0] = make_float2(0.f, 0.f); accB[r][1] = make_float2(0.f, 0.f);
    }

#pragma unroll 4
    for (int k = 0; k < 128; k++) {
        const float4 wa = *(const float4*)&sW[k * 256 + lane * 4];
        const float4 wb = *(const float4*)&sW[k * 256 + 128 + lane * 4];
        const float4 x0 = *(const float4*)&sX[k * XS + w * 8];
        const float4 x1 = *(const float4*)&sX[k * XS + w * 8 + 4];
        float xs[8] = {x0.x, x0.y, x0.z, x0.w, x1.x, x1.y, x1.z, x1.w};
        const float2 wa0 = make_float2(wa.x, wa.y), wa1 = make_float2(wa.z, wa.w);
        const float2 wb0 = make_float2(wb.x, wb.y), wb1 = make_float2(wb.z, wb.w);
#pragma unroll
        for (int r = 0; r < 8; r++) {
            const float2 xx = make_float2(xs[r], xs[r]);
            ffma2(accA[r][0], xx, wa0);
            ffma2(accA[r][1], xx, wa1);
            ffma2(accB[r][0], xx, wb0);
            ffma2(accB[r][1], xx, wb1);
        }
    }

#pragma unroll
    for (int r = 0; r < 8; r++) {
        int row = r0 + w * 8 + r;
        if (row < NN) {
            *(float4*)&g_xl[row * 128 + lane * 4] =
                make_float4(accA[r][0].x, accA[r][0].y, accA[r][1].x, accA[r][1].y);
            *(float4*)&g_xr[row * 128 + lane * 4] =
                make_float4(accB[r][0].x, accB[r][0].y, accB[r][1].x, accB[r][1].y);
        }
    }
}

// ---------------- CSR build --------------------------------------------------
__global__ void zero_cnt_kernel() {
    int i = blockIdx.x * blockDim.x + threadIdx.x;
    if (i < NN) g_cnt[i] = 0;
}

__global__ void hist_kernel(const int* __restrict__ dst) {
    int e = blockIdx.x * blockDim.x + threadIdx.x;
    if (e < NE) atomicAdd(&g_cnt[dst[e]], 1);
}

// Single-block scan, counts staged in smem (coalesced loads; stride-49 smem
// reads are conflict-free since gcd(49,32)=1). Proper shfl block scan.
#define SCAN_CH ((NN + 1023) / 1024)   // 49
#define SCAN_SMEM ((NN + 64) * 4)

__global__ void __launch_bounds__(1024) scan_kernel() {
    extern __shared__ int sc[];          // [NN] counts
    __shared__ int warp_sums[32];

    const int tid = threadIdx.x;
    for (int i = tid; i < NN; i += 1024) sc[i] = g_cnt[i];
    __syncthreads();

    const int base = tid * SCAN_CH;
    int s = 0;
#pragma unroll
    for (int i = 0; i < SCAN_CH; i++) {
        int n = base + i;
        if (n < NN) s += sc[n];
    }

    // intra-warp inclusive scan
    const unsigned FULL = 0xffffffffu;
    const int lane = tid & 31;
    int v = s;
#pragma unroll
    for (int off = 1; off < 32; off <<= 1) {
        int t = __shfl_up_sync(FULL, v, off);
        if (lane >= off) v += t;
    }
    if (lane == 31) warp_sums[tid >> 5] = v;
    __syncthreads();
    if (tid < 32) {
        int w = warp_sums[tid];
#pragma unroll
        for (int off = 1; off < 32; off <<= 1) {
            int t = __shfl_up_sync(FULL, w, off);
            if (tid >= off) w += t;
        }
        warp_sums[tid] = w;
    }
    __syncthreads();
    int excl = v - s + ((tid >= 32) ? warp_sums[(tid >> 5) - 1] : 0);

    int run = excl;
#pragma unroll
    for (int i = 0; i < SCAN_CH; i++) {
        int n = base + i;
        if (n < NN) {
            g_row[n] = run;
            g_cur[n] = run;
            run += sc[n];
        }
    }
}

__global__ void scatter_kernel(const int* __restrict__ src, const int* __restrict__ dst) {
    int e = blockIdx.x * blockDim.x + threadIdx.x;
    if (e < NE) {
        int d = dst[e];
        int pos = atomicAdd(&g_cur[d], 1);
        g_csr[pos] = src[e];
    }
}

// ---------------- fused aggregation: online segment-softmax + ELU + LN ------
// One warp per node. lane layout: head = lane>>3, dims = (lane&7)*4 .. +3.
// Branchless flash-style online softmax + depth-2 gather pipeline.
__device__ __forceinline__ float lrelu(float v) { return v > 0.f ? v : NEG * v; }

__global__ void __launch_bounds__(256) agg_kernel(const float* __restrict__ att,
                                                  const float* __restrict__ bias,
                                                  const float* __restrict__ gamma,
                                                  const float* __restrict__ beta,
                                                  float* __restrict__ out) {
    const int node = blockIdx.x * 8 + (threadIdx.x >> 5);
    if (node >= NN) return;
    const int lane = threadIdx.x & 31;
    const unsigned FULL = 0xffffffffu;

    const float4 a4 = *(const float4*)&att[lane * 4];
    const float4 xr4 = *(const float4*)&g_xr[node * 128 + lane * 4];

    const int start = g_row[node];
    const int deg = g_cnt[node];

    // ---- self-loop (src = node): bootstrap the running softmax ----
    float m, s;
    float4 acc;
    {
        const float4 xl4 = *(const float4*)&g_xl[node * 128 + lane * 4];
        float p = lrelu(xl4.x + xr4.x) * a4.x + lrelu(xl4.y + xr4.y) * a4.y +
                  lrelu(xl4.z + xr4.z) * a4.z + lrelu(xl4.w + xr4.w) * a4.w;
        p += __shfl_xor_sync(FULL, p, 1);
        p += __shfl_xor_sync(FULL, p, 2);
        p += __shfl_xor_sync(FULL, p, 4);
        m = p;
        s = 1.f;
        acc = xl4;
    }

    // ---- CSR edges, chunks of 32, depth-2 prefetch, branchless update ----
    for (int ebase = 0; ebase < deg; ebase += 32) {
        const int idx = ebase + lane;
        const int my_src = (idx < deg) ? g_csr[start + idx] : 0;
        const int cnt = min(32, deg - ebase);

        int src0 = __shfl_sync(FULL, my_src, 0);
        float4 cur = *(const float4*)&g_xl[src0 * 128 + lane * 4];

        for (int i = 0; i < cnt; i++) {
            float4 nxt = cur;
            if (i + 1 < cnt) {                       // warp-uniform
                int sn = __shfl_sync(FULL, my_src, i + 1);
                nxt = *(const float4*)&g_xl[sn * 128 + lane * 4];
            }

            float p = lrelu(cur.x + xr4.x) * a4.x + lrelu(cur.y + xr4.y) * a4.y +
                      lrelu(cur.z + xr4.z) * a4.z + lrelu(cur.w + xr4.w) * a4.w;
            p += __shfl_xor_sync(FULL, p, 1);
            p += __shfl_xor_sync(FULL, p, 2);
            p += __shfl_xor_sync(FULL, p, 4);        // logit per 8-lane head group

            const float nm  = fmaxf(m, p);
            const float sc  = __expf(m - nm);        // == 1 when m >= p
            const float wgt = __expf(p - nm);        // == 1 when p >= m
            s = fmaf(s, sc, wgt);
            acc.x = fmaf(acc.x, sc, wgt * cur.x);
            acc.y = fmaf(acc.y, sc, wgt * cur.y);
            acc.z = fmaf(acc.z, sc, wgt * cur.z);
            acc.w = fmaf(acc.w, sc, wgt * cur.w);
            m = nm;

            cur = nxt;
        }
    }

    // ---- epilogue: normalize, bias, ELU, LayerNorm — all in-warp ----
    const float inv = 1.f / s;
    const float4 b4 = *(const float4*)&bias[lane * 4];
    float4 o;
    o.x = acc.x * inv + b4.x;
    o.y = acc.y * inv + b4.y;
    o.z = acc.z * inv + b4.z;
    o.w = acc.w * inv + b4.w;
    o.x = o.x > 0.f ? o.x : (__expf(o.x) - 1.f);
    o.y = o.y > 0.f ? o.y : (__expf(o.y) - 1.f);
    o.z = o.z > 0.f ? o.z : (__expf(o.z) - 1.f);
    o.w = o.w > 0.f ? o.w : (__expf(o.w) - 1.f);

    float t = o.x + o.y + o.z + o.w;
#pragma unroll
    for (int off = 1; off < 32; off <<= 1) t += __shfl_xor_sync(FULL, t, off);
    const float mu = t * (1.f / 128.f);

    float dx = o.x - mu, dy = o.y - mu, dz = o.z - mu, dw = o.w - mu;
    float v = dx * dx + dy * dy + dz * dz + dw * dw;
#pragma unroll
    for (int off = 1; off < 32; off <<= 1) v += __shfl_xor_sync(FULL, v, off);
    const float rstd = rsqrtf(v * (1.f / 128.f) + LNEPS);

    const float4 g4 = *(const float4*)&gamma[lane * 4];
    const float4 be4 = *(const float4*)&beta[lane * 4];
    o.x = dx * rstd * g4.x + be4.x;
    o.y = dy * rstd * g4.y + be4.y;
    o.z = dz * rstd * g4.z + be4.z;
    o.w = dw * rstd * g4.w + be4.w;
    *(float4*)&out[node * 128 + lane * 4] = o;
}

// ---------------- launch -----------------------------------------------------
extern "C" void kernel_launch(void* const* d_in, const int* in_sizes, int n_in,
                              void* d_out, int out_size) {
    const float* x     = (const float*)d_in[0];
    const int*   ei    = (const int*)d_in[1];   // [2, NE]: src row then dst row
    const float* Wl    = (const float*)d_in[2];
    const float* Wr    = (const float*)d_in[3];
    const float* att   = (const float*)d_in[4];
    const float* bias  = (const float*)d_in[5];
    const float* gamma = (const float*)d_in[6];
    const float* beta  = (const float*)d_in[7];
    float* out = (float*)d_out;

    const int* src = ei;
    const int* dst = ei + NE;

    cudaFuncSetAttribute(gemm_kernel, cudaFuncAttributeMaxDynamicSharedMemorySize, GEMM_SMEM);
    cudaFuncSetAttribute(scan_kernel, cudaFuncAttributeMaxDynamicSharedMemorySize, SCAN_SMEM);

    zero_cnt_kernel<<<(NN + 255) / 256, 256>>>();
    hist_kernel<<<(NE + 255) / 256, 256>>>(dst);
    scan_kernel<<<1, 1024, SCAN_SMEM>>>();
    scatter_kernel<<<(NE + 255) / 256, 256>>>(src, dst);
    gemm_kernel<<<(NN + GR - 1) / GR, 256, GEMM_SMEM>>>(x, Wl, Wr);
    agg_kernel<<<(NN + 7) / 8, 256>>>(att, bias, gamma, beta, out);
}